// round 4
// baseline (speedup 1.0000x reference)
#include <cuda_runtime.h>

// Inverse of phi(t) = sum_k w_k exp(-s_k t):
//   build: one warp per knot (K==32==warpSize), log-space Newton on
//          F(t) = ln phi(t) - ln y (convex -> monotone + quadratic).
//          Stores t* only.
//   solve: per-block 2048-interval LINEAR table (t_j, dt_j) in shared
//          memory -> one random LDS.64 per point (half the wavefront cost
//          of the previous cubic LDS.128). float4 I/O, 2 tiles per thread
//          batched up front.

#define NT 2048                 // intervals; knots = NT+1
#define Y0 0.05f
#define Y1 0.95f
#define DY  ((Y1 - Y0) / (float)NT)
#define INV_DY ((float)NT / (Y1 - Y0))
#define NEWTON_ITERS 10

__device__ float g_tknots[NT + 1];

__global__ void __launch_bounds__(256)
phiinv_build_kernel(const float* __restrict__ w_logits,
                    const float* __restrict__ s_raw) {
    const int lane = threadIdx.x & 31;
    const int warp = (blockIdx.x * blockDim.x + threadIdx.x) >> 5;
    if (warp > NT) return;    // whole warps exit together

    // per-lane mixture params: softmax weight, softplus(+0.1) rate
    float lw = w_logits[lane];
    float m = lw;
    #pragma unroll
    for (int o = 16; o; o >>= 1) m = fmaxf(m, __shfl_xor_sync(0xffffffffu, m, o));
    float ew = __expf(lw - m);
    float wsum = ew;
    #pragma unroll
    for (int o = 16; o; o >>= 1) wsum += __shfl_xor_sync(0xffffffffu, wsum, o);
    float w = ew / wsum;

    float x = s_raw[lane];
    float s = fmaxf(x, 0.0f) + log1pf(__expf(-fabsf(x))) + 0.1f;

    const float yt = Y0 + (float)warp * DY;
    const float ly = __logf(yt);

    float t = 0.0f;
    #pragma unroll 1
    for (int it = 0; it < NEWTON_ITERS; ++it) {
        float ek = __expf(-t * s);
        float a = w * ek;        // -> f  = phi(t)
        float b = a * s;         // -> -phi'(t) > 0
        #pragma unroll
        for (int o = 16; o; o >>= 1) {
            a += __shfl_xor_sync(0xffffffffu, a, o);
            b += __shfl_xor_sync(0xffffffffu, b, o);
        }
        float g = __logf(a) - ly;              // F(t) = ln f - ln y
        t = fmaxf(fmaf(g, a / b, t), 0.0f);    // t - F/F' ; F' = -b/a
    }
    if (lane == 0) g_tknots[warp] = t;
}

__global__ void __launch_bounds__(256, 8)
phiinv_solve_kernel(const float4* __restrict__ y4,
                    float4* __restrict__ out4, int n4, int T) {
    __shared__ float  knot[NT + 1];
    __shared__ float2 coef[NT];

    // stage knots coalesced, then build per-interval (t_j, dt_j)
    for (int j = threadIdx.x; j <= NT; j += 256) knot[j] = g_tknots[j];
    __syncthreads();
    for (int j = threadIdx.x; j < NT; j += 256) {
        float a = knot[j];
        coef[j] = make_float2(a, knot[j + 1] - a);
    }
    __syncthreads();

    const int i0 = blockIdx.x * 256 + threadIdx.x;
    const int i1 = i0 + T;

    float4 ya, yb;
    bool va = (i0 < n4), vb = (i1 < n4);
    if (va) ya = y4[i0];
    if (vb) yb = y4[i1];

    float in[8] = {ya.x, ya.y, ya.z, ya.w, yb.x, yb.y, yb.z, yb.w};
    float r[8];
    #pragma unroll
    for (int c = 0; c < 8; ++c) {
        float u = (in[c] - Y0) * INV_DY;
        int j = (int)u;
        j = min(max(j, 0), NT - 1);
        float fr = u - (float)j;
        float2 cf = coef[j];
        r[c] = fmaf(cf.y, fr, cf.x);
    }
    if (va) out4[i0] = make_float4(r[0], r[1], r[2], r[3]);
    if (vb) out4[i1] = make_float4(r[4], r[5], r[6], r[7]);

    // safety net for unexpected sizes (no-op for N = 2M)
    for (int i = i1 + T; i < n4; i += T) {
        float4 yv = y4[i];
        float yy[4] = {yv.x, yv.y, yv.z, yv.w};
        float rr[4];
        #pragma unroll
        for (int c = 0; c < 4; ++c) {
            float u = (yy[c] - Y0) * INV_DY;
            int j = (int)u;
            j = min(max(j, 0), NT - 1);
            float fr = u - (float)j;
            float2 cf = coef[j];
            rr[c] = fmaf(cf.y, fr, cf.x);
        }
        out4[i] = make_float4(rr[0], rr[1], rr[2], rr[3]);
    }
}

extern "C" void kernel_launch(void* const* d_in, const int* in_sizes, int n_in,
                              void* d_out, int out_size) {
    // y is the large input; the two size-K inputs keep metadata order.
    int yi = 0;
    for (int i = 1; i < n_in; ++i)
        if (in_sizes[i] > in_sizes[yi]) yi = i;
    int small[2], ns = 0;
    for (int i = 0; i < n_in && ns < 2; ++i)
        if (i != yi) small[ns++] = i;

    const float* y  = (const float*)d_in[yi];
    const float* wl = (const float*)d_in[small[0]];
    const float* sr = (const float*)d_in[small[1]];
    float* out = (float*)d_out;
    const int n = in_sizes[yi];

    // Build inverse table: NT+1 warps
    const int bt = 256;
    const int bb = ((NT + 1) * 32 + bt - 1) / bt;
    phiinv_build_kernel<<<bb, bt>>>(wl, sr);

    // Interpolate: 1024 blocks x 256 threads, 2 float4 tiles per thread
    const int n4 = n / 4;             // N = 2M -> 524288
    const int sb = 1024;
    const int st = 256;
    const int T  = sb * st;           // 262144
    phiinv_solve_kernel<<<sb, st>>>((const float4*)y, (float4*)out, n4, T);
}

// round 7
// speedup vs baseline: 1.1376x; 1.1376x over previous
#include <cuda_runtime.h>

// Inverse of phi(t) = sum_k w_k exp(-s_k t):
//   build: one warp per knot (K==32==warpSize), log-space Newton on
//          F(t) = ln phi(t) - ln y (convex -> monotone + quadratic).
//   solve: 1024-interval linear table (t_j, dt_j) in 8KB shared memory.
//          256 blocks x 256 threads; each thread owns 8 float4 tiles with
//          ALL global loads front-batched (MLP=8) so the L2 latency is
//          exposed once per warp, then 32 independent LDS+FMA, then stores.

#define NT 1024                 // intervals; knots = NT+1
#define Y0 0.05f
#define Y1 0.95f
#define DY  ((Y1 - Y0) / (float)NT)
#define INV_DY ((float)NT / (Y1 - Y0))
#define NEWTON_ITERS 10
#define TILES 8                 // float4 tiles per thread

__device__ float g_tknots[NT + 1];

__global__ void __launch_bounds__(256)
phiinv_build_kernel(const float* __restrict__ w_logits,
                    const float* __restrict__ s_raw) {
    const int lane = threadIdx.x & 31;
    const int warp = (blockIdx.x * blockDim.x + threadIdx.x) >> 5;
    if (warp > NT) return;    // whole warps exit together

    // per-lane mixture params: softmax weight, softplus(+0.1) rate
    float lw = w_logits[lane];
    float m = lw;
    #pragma unroll
    for (int o = 16; o; o >>= 1) m = fmaxf(m, __shfl_xor_sync(0xffffffffu, m, o));
    float ew = __expf(lw - m);
    float wsum = ew;
    #pragma unroll
    for (int o = 16; o; o >>= 1) wsum += __shfl_xor_sync(0xffffffffu, wsum, o);
    float w = ew / wsum;

    float x = s_raw[lane];
    float s = fmaxf(x, 0.0f) + log1pf(__expf(-fabsf(x))) + 0.1f;

    const float yt = Y0 + (float)warp * DY;
    const float ly = __logf(yt);

    float t = 0.0f;
    #pragma unroll 1
    for (int it = 0; it < NEWTON_ITERS; ++it) {
        float ek = __expf(-t * s);
        float a = w * ek;        // -> f  = phi(t)
        float b = a * s;         // -> -phi'(t) > 0
        #pragma unroll
        for (int o = 16; o; o >>= 1) {
            a += __shfl_xor_sync(0xffffffffu, a, o);
            b += __shfl_xor_sync(0xffffffffu, b, o);
        }
        float g = __logf(a) - ly;              // F(t) = ln f - ln y
        t = fmaxf(fmaf(g, a / b, t), 0.0f);    // t - F/F' ; F' = -b/a
    }
    if (lane == 0) g_tknots[warp] = t;
}

__device__ __forceinline__ float interp1(float yv, const float2* coef) {
    float u = (yv - Y0) * INV_DY;
    int j = (int)u;
    j = min(max(j, 0), NT - 1);
    float fr = u - (float)j;
    float2 cf = coef[j];
    return fmaf(cf.y, fr, cf.x);
}

__global__ void __launch_bounds__(256)
phiinv_solve_kernel(const float4* __restrict__ y4,
                    float4* __restrict__ out4, int n4, int T) {
    __shared__ float  knot[NT + 1];
    __shared__ float2 coef[NT];

    for (int j = threadIdx.x; j <= NT; j += 256) knot[j] = g_tknots[j];
    __syncthreads();
    for (int j = threadIdx.x; j < NT; j += 256) {
        float a = knot[j];
        coef[j] = make_float2(a, knot[j + 1] - a);
    }
    __syncthreads();

    const int base = blockIdx.x * 256 + threadIdx.x;

    // fast path: all TILES tiles in range (exact for N = 2M)
    if (base + (TILES - 1) * T < n4) {
        float4 v[TILES];
        #pragma unroll
        for (int k = 0; k < TILES; ++k) v[k] = y4[base + k * T];  // MLP=8
        #pragma unroll
        for (int k = 0; k < TILES; ++k) {
            v[k].x = interp1(v[k].x, coef);
            v[k].y = interp1(v[k].y, coef);
            v[k].z = interp1(v[k].z, coef);
            v[k].w = interp1(v[k].w, coef);
        }
        #pragma unroll
        for (int k = 0; k < TILES; ++k) out4[base + k * T] = v[k];
    } else {
        for (int i = base; i < n4; i += T) {
            float4 v = y4[i];
            v.x = interp1(v.x, coef);
            v.y = interp1(v.y, coef);
            v.z = interp1(v.z, coef);
            v.w = interp1(v.w, coef);
            out4[i] = v;
        }
    }
}

extern "C" void kernel_launch(void* const* d_in, const int* in_sizes, int n_in,
                              void* d_out, int out_size) {
    // y is the large input; the two size-K inputs keep metadata order.
    int yi = 0;
    for (int i = 1; i < n_in; ++i)
        if (in_sizes[i] > in_sizes[yi]) yi = i;
    int small[2], ns = 0;
    for (int i = 0; i < n_in && ns < 2; ++i)
        if (i != yi) small[ns++] = i;

    const float* y  = (const float*)d_in[yi];
    const float* wl = (const float*)d_in[small[0]];
    const float* sr = (const float*)d_in[small[1]];
    float* out = (float*)d_out;
    const int n = in_sizes[yi];

    // Build inverse table: NT+1 warps
    const int bt = 256;
    const int bb = ((NT + 1) * 32 + bt - 1) / bt;
    phiinv_build_kernel<<<bb, bt>>>(wl, sr);

    // Interpolate: 256 blocks x 256 threads x 8 float4 each
    const int n4 = n / 4;             // N = 2M -> 524288
    const int sb = 256;
    const int st = 256;
    const int T  = sb * st;           // 65536
    phiinv_solve_kernel<<<sb, st>>>((const float4*)y, (float4*)out, n4, T);
}